// round 8
// baseline (speedup 1.0000x reference)
#include <cuda_runtime.h>
#include <cuda_fp16.h>
#include <cstdint>

// ---------------------------------------------------------------------------
// CrossNetLayer on GB300 (sm_103a; PTX target compute_103 -> no tcgen05)
//   h = x @ W_enc + b_enc  -> mma.sync fp16 GEMM, fp32 accum.
//   W kept in natural [k][n] layout; B fragments loaded via ldmatrix.trans.
//   cross layers via closed form: out = a4(row) * h + u4
// ---------------------------------------------------------------------------

#define BDIM 1024
#define HDIM 1024
#define KDIM 1024
#define DEPTH 4

// Scratch (no cudaMalloc allowed)
__device__ float   g_h[BDIM * HDIM];
__device__ __half  g_x16[BDIM * KDIM];
__device__ __half  g_w16[KDIM * HDIM];   // W in original [k][n] layout, fp16
__device__ float   g_e[DEPTH];           // e_l = u_l . w_l
__device__ float   g_u4[HDIM];           // u_4 = b0+b1+b2+b3

// ---------------------------------------------------------------------------
// helpers
// ---------------------------------------------------------------------------
__device__ __forceinline__ uint32_t smem_u32(const void* p) {
    uint32_t a;
    asm("{ .reg .u64 t; cvta.to.shared.u64 t, %1; cvt.u32.u64 %0, t; }"
        : "=r"(a) : "l"(p));
    return a;
}

__device__ __forceinline__ uint32_t swz(uint32_t off) {
    return off ^ ((off >> 3) & 0x70);   // SW128: 16B granule ^= row&7
}

__device__ __forceinline__ void cp_async16(uint32_t smem_addr, const void* gptr) {
    asm volatile("cp.async.cg.shared.global [%0], [%1], 16;"
                 :: "r"(smem_addr), "l"(gptr));
}

__device__ __forceinline__ void ldsm_x4(uint32_t* r, uint32_t addr) {
    asm volatile("ldmatrix.sync.aligned.m8n8.x4.shared.b16 {%0,%1,%2,%3}, [%4];"
                 : "=r"(r[0]), "=r"(r[1]), "=r"(r[2]), "=r"(r[3]) : "r"(addr));
}

__device__ __forceinline__ void ldsm_x4_t(uint32_t* r, uint32_t addr) {
    asm volatile("ldmatrix.sync.aligned.m8n8.x4.trans.shared.b16 {%0,%1,%2,%3}, [%4];"
                 : "=r"(r[0]), "=r"(r[1]), "=r"(r[2]), "=r"(r[3]) : "r"(addr));
}

__device__ __forceinline__ void mma_f16(float* d, const uint32_t* a, const uint32_t* b) {
    asm volatile(
        "mma.sync.aligned.m16n8k16.row.col.f32.f16.f16.f32 "
        "{%0,%1,%2,%3}, {%4,%5,%6,%7}, {%8,%9}, {%0,%1,%2,%3};"
        : "+f"(d[0]), "+f"(d[1]), "+f"(d[2]), "+f"(d[3])
        : "r"(a[0]), "r"(a[1]), "r"(a[2]), "r"(a[3]), "r"(b[0]), "r"(b[1]));
}

// ---------------------------------------------------------------------------
// Fused precompute (one launch, 513 blocks):
//   blocks [0,256):   x fp32 -> g_x16 (streaming, 16 floats/thread)
//   blocks [256,512): W fp32 -> g_w16 (streaming, layout-preserving)
//   block 512:        e_l and u4
// ---------------------------------------------------------------------------
__global__ __launch_bounds__(256, 1) void precompute_kernel(
    const float* __restrict__ x, const float* __restrict__ W,
    const float* __restrict__ ws, const float* __restrict__ bs)
{
    const int bid = blockIdx.x;
    const int tid = threadIdx.x;

    if (bid < 512) {
        const float* src = (bid < 256) ? x : W;
        __half* dst = (bid < 256) ? g_x16 : g_w16;
        int base = (((bid & 255) * 256) + tid) * 16;
#pragma unroll
        for (int j = 0; j < 4; j++) {
            float4 v = *(const float4*)(src + base + 4 * j);
            __half2* ph = (__half2*)(dst + base + 4 * j);
            ph[0] = __floats2half2_rn(v.x, v.y);
            ph[1] = __floats2half2_rn(v.z, v.w);
        }
        return;
    }

    // ---- block 512: e_l and u4 precompute ----
    __shared__ float esum[3][8];
    const int lane = tid & 31;
    const int wrp = tid >> 5;
    float p1 = 0.f, p2 = 0.f, p3 = 0.f;
#pragma unroll
    for (int j = 0; j < 4; j++) {
        int c = tid * 4 + j;
        float b0 = bs[0 * HDIM + c];
        float b1 = bs[1 * HDIM + c];
        float b2 = bs[2 * HDIM + c];
        float b3 = bs[3 * HDIM + c];
        p1 += b0 * ws[1 * HDIM + c];
        p2 += (b0 + b1) * ws[2 * HDIM + c];
        p3 += (b0 + b1 + b2) * ws[3 * HDIM + c];
        g_u4[c] = b0 + b1 + b2 + b3;
    }
#pragma unroll
    for (int o = 16; o > 0; o >>= 1) {
        p1 += __shfl_xor_sync(0xffffffffu, p1, o);
        p2 += __shfl_xor_sync(0xffffffffu, p2, o);
        p3 += __shfl_xor_sync(0xffffffffu, p3, o);
    }
    if (lane == 0) { esum[0][wrp] = p1; esum[1][wrp] = p2; esum[2][wrp] = p3; }
    __syncthreads();
    if (tid == 0) {
        float e1 = 0.f, e2 = 0.f, e3 = 0.f;
#pragma unroll
        for (int i = 0; i < 8; i++) { e1 += esum[0][i]; e2 += esum[1][i]; e3 += esum[2][i]; }
        g_e[0] = 0.0f; g_e[1] = e1; g_e[2] = e2; g_e[3] = e3;
    }
}

// ---------------------------------------------------------------------------
// mma.sync GEMM: h = x @ W_enc + bias (fp16, fp32 accum)
// CTA tile: BM=128, BN=64, BK=128. Grid (16,8) = 128 CTAs.
// A smem: [m][k], 2 x 64-k sub-tiles (SW128). B smem: [k][n], 128 rows x 128B.
// B fragments via ldmatrix.trans. 8 warps (4M x 2N), warp tile 32x32.
// ---------------------------------------------------------------------------
#define GBM 128
#define GBN 64
#define GKC 128
#define NCHUNK (KDIM / GKC)     // 8

// stage layout (bytes): A[2][16384], B[16384]
#define SUB_A 0
#define SUB_B 32768
#define STAGE_BYTES 49152
#define GEMM_SMEM (2 * STAGE_BYTES)   // 98304

__global__ __launch_bounds__(256, 1) void gemm_mma_kernel(const float* __restrict__ bias)
{
    extern __shared__ char smem[];
    const int tid  = threadIdx.x;
    const int wid  = tid >> 5;
    const int lane = tid & 31;
    const int bn   = blockIdx.x;   // 0..15
    const int bm   = blockIdx.y;   // 0..7
    const uint32_t sb = smem_u32(smem);

    const int warp_m = wid >> 1;   // 0..3
    const int warp_n = wid & 1;    // 0..1

    // ---- A load addressing (advance +256B per chunk) ----
    const char* pA[8]; uint32_t offA[8];
#pragma unroll
    for (int it = 0; it < 8; ++it) {
        int idx = tid + it * 256;
        int row = idx >> 4;          // 0..127 (m)
        int g   = idx & 15;          // 16B granule within 256B k-row
        size_t gb = ((size_t)(bm * GBM + row) * KDIM) * 2 + g * 16;
        pA[it] = (const char*)g_x16 + gb;
        offA[it] = (uint32_t)(g >> 3) * 16384 + swz(row * 128 + (g & 7) * 16);
    }
    // ---- B load addressing (advance +262144B per chunk) ----
    // g_w16 is [k][n]: element (k,n) at byte k*2048 + 2n. Tile: 128 k-rows x 128B.
    const char* pB[4]; uint32_t offB[4];
#pragma unroll
    for (int it = 0; it < 4; ++it) {
        int idx = tid + it * 256;
        int row = idx >> 3;          // 0..127 (k)
        int g   = idx & 7;           // 16B granule within 128B n-row
        pB[it] = (const char*)g_w16 + (size_t)row * 2048 + bn * 128 + g * 16;
        offB[it] = swz(row * 128 + g * 16);
    }

    // ---- ldmatrix per-lane offset components ----
    const int a_row_l = lane & 15;
    const int a_kb_l  = (lane >> 4) << 4;
    // B trans: lane groups 0-7: (k0+l, n0); 8-15: (k8+l, n0); 16-23: (k0+l, n0+8); 24-31: (k8+l, n0+8)
    const int b_krow_l = (lane & 7) + ((lane >> 3) & 1) * 8;
    const int b_nb_l   = (lane >> 4) << 4;    // +16 bytes = +8 n-cols

    float acc[2][4][4];
#pragma unroll
    for (int mi = 0; mi < 2; mi++)
#pragma unroll
        for (int ni = 0; ni < 4; ni++)
#pragma unroll
            for (int j = 0; j < 4; j++) acc[mi][ni][j] = 0.0f;

    // ---- prologue: preload chunk 0 into stage 0 ----
#pragma unroll
    for (int it = 0; it < 8; ++it)
        cp_async16(sb + SUB_A + offA[it], pA[it]);
#pragma unroll
    for (int it = 0; it < 4; ++it)
        cp_async16(sb + SUB_B + offB[it], pB[it]);
    asm volatile("cp.async.commit_group;" ::: "memory");

    for (int c = 0; c < NCHUNK; ++c) {
        asm volatile("cp.async.wait_group 0;" ::: "memory");
        __syncthreads();

        // issue loads for chunk c+1 into the other stage
        if (c + 1 < NCHUNK) {
            uint32_t dst = sb + ((c + 1) & 1) * STAGE_BYTES;
            size_t goA = (size_t)(c + 1) * 256;        // +128 k fp16 along row
            size_t goB = (size_t)(c + 1) * 262144;     // +128 k-rows of 2048B
#pragma unroll
            for (int it = 0; it < 8; ++it)
                cp_async16(dst + SUB_A + offA[it], pA[it] + goA);
#pragma unroll
            for (int it = 0; it < 4; ++it)
                cp_async16(dst + SUB_B + offB[it], pB[it] + goB);
            asm volatile("cp.async.commit_group;" ::: "memory");
        }

        // compute on chunk c: 2 k-sub-tiles x 4 k-steps
        const uint32_t base = sb + (c & 1) * STAGE_BYTES;
#pragma unroll
        for (int sub = 0; sub < 2; sub++) {
            const uint32_t baseA = base + SUB_A + sub * 16384;
            const uint32_t baseB = base + SUB_B;
            const int ksub = sub * 64;
#pragma unroll
            for (int kk = 0; kk < 4; kk++) {
                uint32_t RA[2][4], RB[8];
#pragma unroll
                for (int mi = 0; mi < 2; mi++) {
                    int row = warp_m * 32 + mi * 16 + a_row_l;
                    uint32_t off = swz(row * 128 + kk * 32 + a_kb_l);
                    ldsm_x4(RA[mi], baseA + off);
                }
#pragma unroll
                for (int p = 0; p < 2; p++) {
                    int krow = ksub + kk * 16 + b_krow_l;
                    int nb   = (warp_n * 32 + p * 16) * 2 + b_nb_l;
                    uint32_t off = swz(krow * 128 + nb);
                    ldsm_x4_t(&RB[4 * p], baseB + off);
                }
#pragma unroll
                for (int mi = 0; mi < 2; mi++)
#pragma unroll
                    for (int ni = 0; ni < 4; ni++)
                        mma_f16(acc[mi][ni], RA[mi], &RB[2 * ni]);
            }
        }
        __syncthreads();
    }

    // epilogue: acc -> g_h (+bias)
    const int g = lane >> 2;
    const int t = lane & 3;
#pragma unroll
    for (int mi = 0; mi < 2; mi++) {
        int row0 = bm * GBM + warp_m * 32 + mi * 16 + g;
#pragma unroll
        for (int ni = 0; ni < 4; ni++) {
            int col = bn * GBN + warp_n * 32 + ni * 8 + t * 2;
            float b0 = __ldg(bias + col);
            float b1 = __ldg(bias + col + 1);
            float2 v0 = make_float2(acc[mi][ni][0] + b0, acc[mi][ni][1] + b1);
            float2 v1 = make_float2(acc[mi][ni][2] + b0, acc[mi][ni][3] + b1);
            *(float2*)(g_h + (size_t)row0 * HDIM + col) = v0;
            *(float2*)(g_h + (size_t)(row0 + 8) * HDIM + col) = v1;
        }
    }
}

// ---------------------------------------------------------------------------
// Closed-form cross: 2 rows per 256-thread block, 512 blocks.
// Each thread: 1 float4 per row. out = a4(row)*h + u4.
// ---------------------------------------------------------------------------
__global__ __launch_bounds__(256, 8) void cross_kernel(
    const float* __restrict__ ws, float* __restrict__ out)
{
    const int r0   = blockIdx.x * 2;
    const int r1   = r0 + 1;
    const int tid  = threadIdx.x;     // 0..255
    const int wid  = tid >> 5;        // 0..7
    const int lane = tid & 31;

    __shared__ float red[8][8];       // [warp][row*4+layer]

    const float4* h0p = (const float4*)(g_h + (size_t)r0 * HDIM);
    const float4* h1p = (const float4*)(g_h + (size_t)r1 * HDIM);
    float4 a0 = h0p[tid];
    float4 b0 = h1p[tid];
    const float4* up = (const float4*)g_u4;
    float4 u0 = up[tid];

    float p[DEPTH], q[DEPTH];
#pragma unroll
    for (int l = 0; l < DEPTH; l++) {
        const float4* wp = (const float4*)(ws + l * HDIM);
        float4 wa = wp[tid];
        p[l] = a0.x * wa.x + a0.y * wa.y + a0.z * wa.z + a0.w * wa.w;
        q[l] = b0.x * wa.x + b0.y * wa.y + b0.z * wa.z + b0.w * wa.w;
    }
#pragma unroll
    for (int o = 16; o > 0; o >>= 1) {
#pragma unroll
        for (int l = 0; l < DEPTH; l++) {
            p[l] += __shfl_xor_sync(0xffffffffu, p[l], o);
            q[l] += __shfl_xor_sync(0xffffffffu, q[l], o);
        }
    }
    if (lane == 0) {
#pragma unroll
        for (int l = 0; l < DEPTH; l++) {
            red[wid][l] = p[l];
            red[wid][4 + l] = q[l];
        }
    }
    __syncthreads();

    float aA = 1.0f, aB = 1.0f;
#pragma unroll
    for (int l = 0; l < DEPTH; l++) {
        float e = g_e[l];
        float dA = 0.f, dB = 0.f;
#pragma unroll
        for (int w = 0; w < 8; w++) { dA += red[w][l]; dB += red[w][4 + l]; }
        aA += aA * dA + e;
        aB += aB * dB + e;
    }

    float4 o0, o1;
    o0.x = fmaf(aA, a0.x, u0.x); o0.y = fmaf(aA, a0.y, u0.y);
    o0.z = fmaf(aA, a0.z, u0.z); o0.w = fmaf(aA, a0.w, u0.w);
    o1.x = fmaf(aB, b0.x, u0.x); o1.y = fmaf(aB, b0.y, u0.y);
    o1.z = fmaf(aB, b0.z, u0.z); o1.w = fmaf(aB, b0.w, u0.w);

    ((float4*)(out + (size_t)r0 * HDIM))[tid] = o0;
    ((float4*)(out + (size_t)r1 * HDIM))[tid] = o1;
}

// ---------------------------------------------------------------------------
extern "C" void kernel_launch(void* const* d_in, const int* in_sizes, int n_in,
                              void* d_out, int out_size)
{
    const float* x     = (const float*)d_in[0];
    const float* W_enc = (const float*)d_in[1];
    const float* b_enc = (const float*)d_in[2];
    const float* ws    = (const float*)d_in[3];
    const float* bs    = (const float*)d_in[4];
    float* out = (float*)d_out;

    cudaFuncSetAttribute(gemm_mma_kernel,
                         cudaFuncAttributeMaxDynamicSharedMemorySize, GEMM_SMEM);

    precompute_kernel<<<513, 256>>>(x, W_enc, ws, bs);
    gemm_mma_kernel<<<dim3(HDIM / GBN, BDIM / GBM), 256, GEMM_SMEM>>>(b_enc);
    cross_kernel<<<BDIM / 2, 256>>>(ws, out);
}

// round 9
// speedup vs baseline: 1.2993x; 1.2993x over previous
#include <cuda_runtime.h>
#include <cuda_fp16.h>
#include <cstdint>

// ---------------------------------------------------------------------------
// CrossNetLayer on GB300 (sm_103a; PTX target compute_103 -> no tcgen05)
//   h = x @ W_enc + b_enc  -> mma.sync fp16 GEMM, fp32 accum.
//   W kept in natural [k][n] layout; B fragments loaded via ldmatrix.trans.
//   cross layers via closed form: out = a4(row) * h + u4
// ---------------------------------------------------------------------------

#define BDIM 1024
#define HDIM 1024
#define KDIM 1024
#define DEPTH 4

// Scratch (no cudaMalloc allowed)
__device__ float   g_h[BDIM * HDIM];
__device__ __half  g_x16[BDIM * KDIM];
__device__ __half  g_w16[KDIM * HDIM];   // W in original [k][n] layout, fp16
__device__ float   g_e[DEPTH];           // e_l = u_l . w_l
__device__ float   g_u4[HDIM];           // u_4 = b0+b1+b2+b3

// ---------------------------------------------------------------------------
// helpers
// ---------------------------------------------------------------------------
__device__ __forceinline__ uint32_t smem_u32(const void* p) {
    uint32_t a;
    asm("{ .reg .u64 t; cvta.to.shared.u64 t, %1; cvt.u32.u64 %0, t; }"
        : "=r"(a) : "l"(p));
    return a;
}

__device__ __forceinline__ uint32_t swz(uint32_t off) {
    return off ^ ((off >> 3) & 0x70);   // SW128: 16B granule ^= row&7
}

__device__ __forceinline__ void cp_async16(uint32_t smem_addr, const void* gptr) {
    asm volatile("cp.async.cg.shared.global [%0], [%1], 16;"
                 :: "r"(smem_addr), "l"(gptr));
}

__device__ __forceinline__ void ldsm_x4(uint32_t* r, uint32_t addr) {
    asm volatile("ldmatrix.sync.aligned.m8n8.x4.shared.b16 {%0,%1,%2,%3}, [%4];"
                 : "=r"(r[0]), "=r"(r[1]), "=r"(r[2]), "=r"(r[3]) : "r"(addr));
}

__device__ __forceinline__ void ldsm_x4_t(uint32_t* r, uint32_t addr) {
    asm volatile("ldmatrix.sync.aligned.m8n8.x4.trans.shared.b16 {%0,%1,%2,%3}, [%4];"
                 : "=r"(r[0]), "=r"(r[1]), "=r"(r[2]), "=r"(r[3]) : "r"(addr));
}

__device__ __forceinline__ void mma_f16(float* d, const uint32_t* a, const uint32_t* b) {
    asm volatile(
        "mma.sync.aligned.m16n8k16.row.col.f32.f16.f16.f32 "
        "{%0,%1,%2,%3}, {%4,%5,%6,%7}, {%8,%9}, {%0,%1,%2,%3};"
        : "+f"(d[0]), "+f"(d[1]), "+f"(d[2]), "+f"(d[3])
        : "r"(a[0]), "r"(a[1]), "r"(a[2]), "r"(a[3]), "r"(b[0]), "r"(b[1]));
}

// ---------------------------------------------------------------------------
// Fused precompute (one launch, 2049 thin blocks, 4 floats/thread):
//   blocks [0,1024):    x fp32 -> g_x16 (streaming)
//   blocks [1024,2048): W fp32 -> g_w16 (streaming, layout-preserving)
//   block 2048:         e_l and u4
// ---------------------------------------------------------------------------
__global__ __launch_bounds__(256, 1) void precompute_kernel(
    const float* __restrict__ x, const float* __restrict__ W,
    const float* __restrict__ ws, const float* __restrict__ bs)
{
    const int bid = blockIdx.x;
    const int tid = threadIdx.x;

    if (bid < 2048) {
        const float* src = (bid < 1024) ? x : W;
        __half* dst = (bid < 1024) ? g_x16 : g_w16;
        int i = (((bid & 1023) * 256) + tid) * 4;
        float4 v = *(const float4*)(src + i);
        __half2* ph = (__half2*)(dst + i);
        ph[0] = __floats2half2_rn(v.x, v.y);
        ph[1] = __floats2half2_rn(v.z, v.w);
        return;
    }

    // ---- block 2048: e_l and u4 precompute ----
    __shared__ float esum[3][8];
    const int lane = tid & 31;
    const int wrp = tid >> 5;
    float p1 = 0.f, p2 = 0.f, p3 = 0.f;
#pragma unroll
    for (int j = 0; j < 4; j++) {
        int c = tid * 4 + j;
        float b0 = bs[0 * HDIM + c];
        float b1 = bs[1 * HDIM + c];
        float b2 = bs[2 * HDIM + c];
        float b3 = bs[3 * HDIM + c];
        p1 += b0 * ws[1 * HDIM + c];
        p2 += (b0 + b1) * ws[2 * HDIM + c];
        p3 += (b0 + b1 + b2) * ws[3 * HDIM + c];
        g_u4[c] = b0 + b1 + b2 + b3;
    }
#pragma unroll
    for (int o = 16; o > 0; o >>= 1) {
        p1 += __shfl_xor_sync(0xffffffffu, p1, o);
        p2 += __shfl_xor_sync(0xffffffffu, p2, o);
        p3 += __shfl_xor_sync(0xffffffffu, p3, o);
    }
    if (lane == 0) { esum[0][wrp] = p1; esum[1][wrp] = p2; esum[2][wrp] = p3; }
    __syncthreads();
    if (tid == 0) {
        float e1 = 0.f, e2 = 0.f, e3 = 0.f;
#pragma unroll
        for (int i = 0; i < 8; i++) { e1 += esum[0][i]; e2 += esum[1][i]; e3 += esum[2][i]; }
        g_e[0] = 0.0f; g_e[1] = e1; g_e[2] = e2; g_e[3] = e3;
    }
}

// ---------------------------------------------------------------------------
// mma.sync GEMM: h = x @ W_enc + bias (fp16, fp32 accum)
// CTA tile: BM=128, BN=64, BK=128. Grid (16,8) = 128 CTAs.
// A smem: [m][k], 2 x 64-k sub-tiles (SW128). B smem: [k][n], 128 rows x 128B.
// B fragments via ldmatrix.trans. 8 warps (4M x 2N), warp tile 32x32.
// ---------------------------------------------------------------------------
#define GBM 128
#define GBN 64
#define GKC 128
#define NCHUNK (KDIM / GKC)     // 8

// stage layout (bytes): A[2][16384], B[16384]
#define SUB_A 0
#define SUB_B 32768
#define STAGE_BYTES 49152
#define GEMM_SMEM (2 * STAGE_BYTES)   // 98304

__global__ __launch_bounds__(256, 1) void gemm_mma_kernel(const float* __restrict__ bias)
{
    extern __shared__ char smem[];
    const int tid  = threadIdx.x;
    const int wid  = tid >> 5;
    const int lane = tid & 31;
    const int bn   = blockIdx.x;   // 0..15
    const int bm   = blockIdx.y;   // 0..7
    const uint32_t sb = smem_u32(smem);

    const int warp_m = wid >> 1;   // 0..3
    const int warp_n = wid & 1;    // 0..1

    // ---- A load addressing (advance +256B per chunk) ----
    const char* pA[8]; uint32_t offA[8];
#pragma unroll
    for (int it = 0; it < 8; ++it) {
        int idx = tid + it * 256;
        int row = idx >> 4;          // 0..127 (m)
        int g   = idx & 15;          // 16B granule within 256B k-row
        size_t gb = ((size_t)(bm * GBM + row) * KDIM) * 2 + g * 16;
        pA[it] = (const char*)g_x16 + gb;
        offA[it] = (uint32_t)(g >> 3) * 16384 + swz(row * 128 + (g & 7) * 16);
    }
    // ---- B load addressing (advance +262144B per chunk) ----
    // g_w16 is [k][n]: element (k,n) at byte k*2048 + 2n. Tile: 128 k-rows x 128B.
    const char* pB[4]; uint32_t offB[4];
#pragma unroll
    for (int it = 0; it < 4; ++it) {
        int idx = tid + it * 256;
        int row = idx >> 3;          // 0..127 (k)
        int g   = idx & 7;           // 16B granule within 128B n-row
        pB[it] = (const char*)g_w16 + (size_t)row * 2048 + bn * 128 + g * 16;
        offB[it] = swz(row * 128 + g * 16);
    }

    // ---- ldmatrix per-lane offset components ----
    const int a_row_l = lane & 15;
    const int a_kb_l  = (lane >> 4) << 4;
    const int b_krow_l = (lane & 7) + ((lane >> 3) & 1) * 8;
    const int b_nb_l   = (lane >> 4) << 4;    // +16 bytes = +8 n-cols

    float acc[2][4][4];
#pragma unroll
    for (int mi = 0; mi < 2; mi++)
#pragma unroll
        for (int ni = 0; ni < 4; ni++)
#pragma unroll
            for (int j = 0; j < 4; j++) acc[mi][ni][j] = 0.0f;

    // ---- prologue: preload chunk 0 into stage 0 ----
#pragma unroll
    for (int it = 0; it < 8; ++it)
        cp_async16(sb + SUB_A + offA[it], pA[it]);
#pragma unroll
    for (int it = 0; it < 4; ++it)
        cp_async16(sb + SUB_B + offB[it], pB[it]);
    asm volatile("cp.async.commit_group;" ::: "memory");

    for (int c = 0; c < NCHUNK; ++c) {
        asm volatile("cp.async.wait_group 0;" ::: "memory");
        __syncthreads();

        // issue loads for chunk c+1 into the other stage
        if (c + 1 < NCHUNK) {
            uint32_t dst = sb + ((c + 1) & 1) * STAGE_BYTES;
            size_t goA = (size_t)(c + 1) * 256;        // +128 k fp16 along row
            size_t goB = (size_t)(c + 1) * 262144;     // +128 k-rows of 2048B
#pragma unroll
            for (int it = 0; it < 8; ++it)
                cp_async16(dst + SUB_A + offA[it], pA[it] + goA);
#pragma unroll
            for (int it = 0; it < 4; ++it)
                cp_async16(dst + SUB_B + offB[it], pB[it] + goB);
            asm volatile("cp.async.commit_group;" ::: "memory");
        }

        // compute on chunk c: 2 k-sub-tiles x 4 k-steps
        const uint32_t base = sb + (c & 1) * STAGE_BYTES;
#pragma unroll
        for (int sub = 0; sub < 2; sub++) {
            const uint32_t baseA = base + SUB_A + sub * 16384;
            const uint32_t baseB = base + SUB_B;
            const int ksub = sub * 64;
#pragma unroll
            for (int kk = 0; kk < 4; kk++) {
                uint32_t RA[2][4], RB[8];
#pragma unroll
                for (int mi = 0; mi < 2; mi++) {
                    int row = warp_m * 32 + mi * 16 + a_row_l;
                    uint32_t off = swz(row * 128 + kk * 32 + a_kb_l);
                    ldsm_x4(RA[mi], baseA + off);
                }
#pragma unroll
                for (int p = 0; p < 2; p++) {
                    int krow = ksub + kk * 16 + b_krow_l;
                    int nb   = (warp_n * 32 + p * 16) * 2 + b_nb_l;
                    uint32_t off = swz(krow * 128 + nb);
                    ldsm_x4_t(&RB[4 * p], baseB + off);
                }
#pragma unroll
                for (int mi = 0; mi < 2; mi++)
#pragma unroll
                    for (int ni = 0; ni < 4; ni++)
                        mma_f16(acc[mi][ni], RA[mi], &RB[2 * ni]);
            }
        }
        __syncthreads();
    }

    // epilogue: acc -> g_h (+bias)
    const int g = lane >> 2;
    const int t = lane & 3;
#pragma unroll
    for (int mi = 0; mi < 2; mi++) {
        int row0 = bm * GBM + warp_m * 32 + mi * 16 + g;
#pragma unroll
        for (int ni = 0; ni < 4; ni++) {
            int col = bn * GBN + warp_n * 32 + ni * 8 + t * 2;
            float b0 = __ldg(bias + col);
            float b1 = __ldg(bias + col + 1);
            float2 v0 = make_float2(acc[mi][ni][0] + b0, acc[mi][ni][1] + b1);
            float2 v1 = make_float2(acc[mi][ni][2] + b0, acc[mi][ni][3] + b1);
            *(float2*)(g_h + (size_t)row0 * HDIM + col) = v0;
            *(float2*)(g_h + (size_t)(row0 + 8) * HDIM + col) = v1;
        }
    }
}

// ---------------------------------------------------------------------------
// Closed-form cross (R7-measured config): 2 rows per 128-thread block.
// out = a4(row)*h + u4 ; a recurrence from 4 parallel dots + precomputed e_l.
// ---------------------------------------------------------------------------
__global__ __launch_bounds__(128, 8) void cross_kernel(
    const float* __restrict__ ws, float* __restrict__ out)
{
    const int r0   = blockIdx.x * 2;
    const int r1   = r0 + 1;
    const int tid  = threadIdx.x;     // 0..127
    const int wid  = tid >> 5;
    const int lane = tid & 31;

    __shared__ float red[4][8];       // [warp][row*4+layer]

    const float4* h0p = (const float4*)(g_h + (size_t)r0 * HDIM);
    const float4* h1p = (const float4*)(g_h + (size_t)r1 * HDIM);
    float4 a0 = h0p[tid];
    float4 a1 = h0p[tid + 128];
    float4 b0 = h1p[tid];
    float4 b1 = h1p[tid + 128];
    const float4* up = (const float4*)g_u4;
    float4 u0 = up[tid];
    float4 u1 = up[tid + 128];

    float p[DEPTH], q[DEPTH];
#pragma unroll
    for (int l = 0; l < DEPTH; l++) {
        const float4* wp = (const float4*)(ws + l * HDIM);
        float4 wa = wp[tid];
        float4 wb = wp[tid + 128];
        p[l] = a0.x * wa.x + a0.y * wa.y + a0.z * wa.z + a0.w * wa.w
             + a1.x * wb.x + a1.y * wb.y + a1.z * wb.z + a1.w * wb.w;
        q[l] = b0.x * wa.x + b0.y * wa.y + b0.z * wa.z + b0.w * wa.w
             + b1.x * wb.x + b1.y * wb.y + b1.z * wb.z + b1.w * wb.w;
    }
#pragma unroll
    for (int o = 16; o > 0; o >>= 1) {
#pragma unroll
        for (int l = 0; l < DEPTH; l++) {
            p[l] += __shfl_xor_sync(0xffffffffu, p[l], o);
            q[l] += __shfl_xor_sync(0xffffffffu, q[l], o);
        }
    }
    if (lane == 0) {
#pragma unroll
        for (int l = 0; l < DEPTH; l++) {
            red[wid][l] = p[l];
            red[wid][4 + l] = q[l];
        }
    }
    __syncthreads();

    float aA = 1.0f, aB = 1.0f;
#pragma unroll
    for (int l = 0; l < DEPTH; l++) {
        float e = g_e[l];
        float dA = red[0][l] + red[1][l] + red[2][l] + red[3][l];
        float dB = red[0][4 + l] + red[1][4 + l] + red[2][4 + l] + red[3][4 + l];
        aA += aA * dA + e;
        aB += aB * dB + e;
    }

    float4 o0, o1, o2, o3;
    o0.x = fmaf(aA, a0.x, u0.x); o0.y = fmaf(aA, a0.y, u0.y);
    o0.z = fmaf(aA, a0.z, u0.z); o0.w = fmaf(aA, a0.w, u0.w);
    o1.x = fmaf(aA, a1.x, u1.x); o1.y = fmaf(aA, a1.y, u1.y);
    o1.z = fmaf(aA, a1.z, u1.z); o1.w = fmaf(aA, a1.w, u1.w);
    o2.x = fmaf(aB, b0.x, u0.x); o2.y = fmaf(aB, b0.y, u0.y);
    o2.z = fmaf(aB, b0.z, u0.z); o2.w = fmaf(aB, b0.w, u0.w);
    o3.x = fmaf(aB, b1.x, u1.x); o3.y = fmaf(aB, b1.y, u1.y);
    o3.z = fmaf(aB, b1.z, u1.z); o3.w = fmaf(aB, b1.w, u1.w);

    float4* op0 = (float4*)(out + (size_t)r0 * HDIM);
    float4* op1 = (float4*)(out + (size_t)r1 * HDIM);
    op0[tid] = o0;
    op0[tid + 128] = o1;
    op1[tid] = o2;
    op1[tid + 128] = o3;
}

// ---------------------------------------------------------------------------
extern "C" void kernel_launch(void* const* d_in, const int* in_sizes, int n_in,
                              void* d_out, int out_size)
{
    const float* x     = (const float*)d_in[0];
    const float* W_enc = (const float*)d_in[1];
    const float* b_enc = (const float*)d_in[2];
    const float* ws    = (const float*)d_in[3];
    const float* bs    = (const float*)d_in[4];
    float* out = (float*)d_out;

    cudaFuncSetAttribute(gemm_mma_kernel,
                         cudaFuncAttributeMaxDynamicSharedMemorySize, GEMM_SMEM);

    precompute_kernel<<<2049, 256>>>(x, W_enc, ws, bs);
    gemm_mma_kernel<<<dim3(HDIM / GBN, BDIM / GBM), 256, GEMM_SMEM>>>(b_enc);
    cross_kernel<<<BDIM / 2, 128>>>(ws, out);
}